// round 15
// baseline (speedup 1.0000x reference)
#include <cuda_runtime.h>
#include <cuda_fp16.h>
#include <cstdint>

static const int HB = 1024;   // hidden
static const int NB = 32;     // batch
static const int SS = 2048;   // seq
static const int MT = NB * SS;

__device__ float g_qproj[NB * HB];
__device__ float g_scores_part[16 * NB * SS];      // [bx*4+wn][m]
__device__ uint4 g_keys_h4[(size_t)NB * SS * HB / 8];  // keys as fp16 (filled by score)
__device__ uint4 g_ua_h4[HB * HB / 8];                 // Ua as fp16, 2MB

// ---------------------------------------------------------------------------
__device__ __forceinline__ uint32_t smem_u32(const void* p) {
    uint32_t a;
    asm("{ .reg .u64 t; cvta.to.shared.u64 t, %1; cvt.u32.u64 %0, t; }"
        : "=r"(a) : "l"(p));
    return a;
}

__device__ __forceinline__ void ldsm4(uint32_t* r, uint32_t addr) {
    asm volatile("ldmatrix.sync.aligned.m8n8.x4.shared.b16 {%0,%1,%2,%3}, [%4];"
                 : "=r"(r[0]), "=r"(r[1]), "=r"(r[2]), "=r"(r[3]) : "r"(addr));
}

__device__ __forceinline__ void mma16816(float* d, const uint32_t* a,
                                         uint32_t b0, uint32_t b1) {
    asm volatile(
        "mma.sync.aligned.m16n8k16.row.col.f32.f16.f16.f32 "
        "{%0,%1,%2,%3}, {%4,%5,%6,%7}, {%8,%9}, {%0,%1,%2,%3};"
        : "+f"(d[0]), "+f"(d[1]), "+f"(d[2]), "+f"(d[3])
        : "r"(a[0]), "r"(a[1]), "r"(a[2]), "r"(a[3]), "r"(b0), "r"(b1));
}

__device__ __forceinline__ void cpasync16(uint32_t saddr, const void* gaddr) {
    asm volatile("cp.async.cg.shared.global [%0], [%1], 16;"
                 :: "r"(saddr), "l"(gaddr));
}

__device__ __forceinline__ float fast_tanh(float x) {
    float y;
    asm("tanh.approx.f32 %0, %1;" : "=f"(y) : "f"(x));
    return y;
}

// fp32 -> fp16, 8 values -> one 16B word
__device__ __forceinline__ void cvt8_h(float4 a, float4 b, uint4& hi) {
    __half2 h0 = __float22half2_rn(make_float2(a.x, a.y));
    __half2 h1 = __float22half2_rn(make_float2(a.z, a.w));
    __half2 h2 = __float22half2_rn(make_float2(b.x, b.y));
    __half2 h3 = __float22half2_rn(make_float2(b.z, b.w));
    hi.x = *(uint32_t*)&h0; hi.y = *(uint32_t*)&h1;
    hi.z = *(uint32_t*)&h2; hi.w = *(uint32_t*)&h3;
}

// ---------------------------------------------------------------------------
__global__ void cvt_ua_kernel(const float* __restrict__ src) {
    size_t i = (size_t)blockIdx.x * blockDim.x + threadIdx.x;
    const float4* p = (const float4*)src + i * 2;
    float4 a = p[0], b = p[1];
    uint4 h; cvt8_h(a, b, h);
    g_ua_h4[i] = h;
}

// ---------------------------------------------------------------------------
__global__ void init_kernel(float* __restrict__ ctx) {
    int i = blockIdx.x * blockDim.x + threadIdx.x;
    if (i < NB * HB) ctx[i] = 0.0f;
}

// ---------------------------------------------------------------------------
__global__ void qproj_kernel(const float* __restrict__ query,
                             const float* __restrict__ Wa_w,
                             const float* __restrict__ Wa_b) {
    int b = blockIdx.y;
    int warp = threadIdx.x >> 5;
    int lane = threadIdx.x & 31;
    int k = blockIdx.x * 8 + warp;
    const float* q = query + b * HB;
    const float* w = Wa_w + k * HB;
    float acc = 0.0f;
#pragma unroll
    for (int i = 0; i < HB / 32; i++)
        acc += q[lane + 32 * i] * w[lane + 32 * i];
#pragma unroll
    for (int o = 16; o; o >>= 1)
        acc += __shfl_xor_sync(0xffffffffu, acc, o);
    if (lane == 0) g_qproj[b * HB + k] = acc + Wa_b[k];
}

// ---------------------------------------------------------------------------
// score GEMM: CTA tile 128(m) x 256(n), K-chunk 64, 512 thr (16 warps 4x4,
// warp tile 32x64). B: 4-stage cp.async fp16 ring. A: fp32 keys loaded via
// LDG, converted to fp16 in registers (1-chunk prefetch), STS to a 2-stage
// buffer; bx==0 CTAs also persist fp16 keys to gmem for the context kernel.
// Epilogue fuses tanh + Va dot via __ldg -> atomic-free partials.
// ---------------------------------------------------------------------------
#define RSTRIDE 144
#define TA_SZ 18432
#define TB_BASE 36864
#define TB_SZ 36864
#define NSTG 4
#define SMEM_BYTES 184320
#define NCH 16

__global__ __launch_bounds__(512, 1)
void score_kernel(const float* __restrict__ keys,
                  const float* __restrict__ Ua_b,
                  const float* __restrict__ Va_w) {
    extern __shared__ __align__(16) char smem[];
    const uint32_t sb = smem_u32(smem);
    const int tid = threadIdx.x;
    const int wid = tid >> 5, lane = tid & 31;
    const int lane16 = lane & 15, laneh = lane >> 4;
    const int n0 = blockIdx.x * 256;
    const int m0 = blockIdx.y * 128;
    const int b = m0 >> 11;                 // 128 | 2048

    const int wm = wid & 3, wn = wid >> 2;  // 4x4 warp grid, warp = 32m x 64n
    const int wrow0 = wm * 32, wcol0 = wn * 64;

    const float* gA = keys + (size_t)m0 * HB;            // fp32 source
    const __half* gB = (const __half*)g_ua_h4 + (size_t)n0 * HB;
    const bool writeK = (blockIdx.x == 0);

    // A mapping: unit = 8 halves (16B dst / 32B src); 1024 units, 2/thread
    // unit = tid + 512r -> row = (tid>>3) + 64r, u = tid&7
    const int arow = tid >> 3, au = tid & 7;
    const uint32_t aDst = arow * RSTRIDE + au * 16;      // + 64*RSTRIDE for r=1
    const size_t aSrc = (size_t)arow * HB + au * 8;      // + 64*HB for r=1

    // B cp.async: 2048 units, 4/thread
    const uint32_t bDst = TB_BASE + (tid >> 3) * RSTRIDE + (tid & 7) * 16;
    const size_t bSrc = (size_t)(tid >> 3) * HB + (tid & 7) * 8;

    auto issueB = [&](int c) {
        const uint32_t sbase = (c & (NSTG - 1)) * TB_SZ;
        const int k0 = c * 64;
#pragma unroll
        for (int r = 0; r < 4; r++)
            cpasync16(sb + bDst + sbase + r * (64 * RSTRIDE),
                      gB + bSrc + (size_t)r * 64 * HB + k0);
        asm volatile("cp.async.commit_group;" ::: "memory");
    };

    // load fp32 A chunk c, convert to fp16 in regs
    auto loadA = [&](int c, uint4* av) {
        const int k0 = c * 64;
#pragma unroll
        for (int r = 0; r < 2; r++) {
            const float4* p = (const float4*)(gA + aSrc + (size_t)r * 64 * HB + k0);
            float4 x = p[0], y = p[1];
            cvt8_h(x, y, av[r]);
        }
    };
    auto stsA = [&](int c, const uint4* av) {
        const uint32_t sbase = (c & 1) * TA_SZ;
        *(uint4*)(smem + sbase + aDst) = av[0];
        *(uint4*)(smem + sbase + aDst + 64 * RSTRIDE) = av[1];
        if (writeK) {
            uint4* kd = (uint4*)((__half*)g_keys_h4 + (size_t)m0 * HB + c * 64);
            kd[(aSrc) / 8] = av[0];
            kd[(aSrc + (size_t)64 * HB) / 8] = av[1];
        }
    };

    float acc[2][8][4];
#pragma unroll
    for (int mi = 0; mi < 2; mi++)
#pragma unroll
        for (int j = 0; j < 8; j++)
#pragma unroll
            for (int r = 0; r < 4; r++) acc[mi][j][r] = 0.0f;

    uint4 aval[2];
    loadA(0, aval);
    stsA(0, aval);
    loadA(1, aval);
    issueB(0);
    issueB(1);
    issueB(2);

    const uint32_t aAoff = (wrow0 + lane16) * RSTRIDE + laneh * 16;
    const uint32_t aBoff = TB_BASE + (wcol0 + lane16) * RSTRIDE + laneh * 16;

#pragma unroll 1
    for (int c = 0; c < NCH; c++) {
        if (c < NCH - 3)
            asm volatile("cp.async.wait_group 2;" ::: "memory");
        else if (c < NCH - 1)
            asm volatile("cp.async.wait_group 1;" ::: "memory");
        else
            asm volatile("cp.async.wait_group 0;" ::: "memory");
        __syncthreads();

        const uint32_t aA = sb + (c & 1) * TA_SZ + aAoff;
        const uint32_t aB = sb + (c & (NSTG - 1)) * TB_SZ + aBoff;

#pragma unroll
        for (int ks = 0; ks < 4; ks++) {
            const uint32_t kb = ks * 32;
            uint32_t ah[2][4];
            ldsm4(ah[0], aA + kb);
            ldsm4(ah[1], aA + kb + 16 * RSTRIDE);
#pragma unroll
            for (int nj = 0; nj < 4; nj++) {
                uint32_t bh[4];
                ldsm4(bh, aB + kb + nj * 16 * RSTRIDE);
#pragma unroll
                for (int h = 0; h < 2; h++) {
                    const int j = nj * 2 + h;
                    mma16816(acc[0][j], ah[0], bh[h], bh[h + 2]);
                    mma16816(acc[1][j], ah[1], bh[h], bh[h + 2]);
                }
            }
        }

        // stage A for chunk c+1 (stage (c+1)&1 was last read at chunk c-1)
        if (c + 1 < NCH) stsA(c + 1, aval);
        if (c + 2 < NCH) loadA(c + 2, aval);
        if (c + 3 < NCH) issueB(c + 3);
    }

    // epilogue: part[row] = sum_n Va[n] * tanh(acc + qproj[b,n] + Ua_b[n])
#pragma unroll
    for (int mi = 0; mi < 2; mi++) {
        float pr0 = 0.0f, pr1 = 0.0f;
#pragma unroll
        for (int j = 0; j < 8; j++) {
            int n = n0 + wcol0 + j * 8 + (lane & 3) * 2;
            float2 qp = __ldg((const float2*)(g_qproj + b * HB + n));
            float2 ub = __ldg((const float2*)(Ua_b + n));
            float2 va = __ldg((const float2*)(Va_w + n));
            float q0 = qp.x + ub.x, q1 = qp.y + ub.y;
            pr0 += va.x * fast_tanh(acc[mi][j][0] + q0)
                 + va.y * fast_tanh(acc[mi][j][1] + q1);
            pr1 += va.x * fast_tanh(acc[mi][j][2] + q0)
                 + va.y * fast_tanh(acc[mi][j][3] + q1);
        }
        pr0 += __shfl_xor_sync(0xffffffffu, pr0, 1);
        pr0 += __shfl_xor_sync(0xffffffffu, pr0, 2);
        pr1 += __shfl_xor_sync(0xffffffffu, pr1, 1);
        pr1 += __shfl_xor_sync(0xffffffffu, pr1, 2);
        if ((lane & 3) == 0) {
            int row = m0 + wrow0 + mi * 16 + (lane >> 2);
            int pidx = blockIdx.x * 4 + wn;
            g_scores_part[pidx * MT + row] = pr0;
            g_scores_part[pidx * MT + row + 8] = pr1;
        }
    }
}

// ---------------------------------------------------------------------------
// softmax: scores[m] = sum of 16 partials + Va_b, then softmax over S
// ---------------------------------------------------------------------------
__global__ void softmax_kernel(float* __restrict__ wout, const float* __restrict__ Va_b) {
    int b = blockIdx.x;
    int tid = threadIdx.x;
    int lane = tid & 31, warp = tid >> 5;
    float vb = Va_b[0];

    float v[4];
    float mx = -3.4e38f;
#pragma unroll
    for (int i = 0; i < 4; i++) {
        int m = b * SS + tid + i * 512;
        float s = vb;
#pragma unroll
        for (int p = 0; p < 16; p++) s += g_scores_part[p * MT + m];
        v[i] = s;
        mx = fmaxf(mx, v[i]);
    }
#pragma unroll
    for (int o = 16; o; o >>= 1)
        mx = fmaxf(mx, __shfl_xor_sync(0xffffffffu, mx, o));

    __shared__ float sm[16];
    if (lane == 0) sm[warp] = mx;
    __syncthreads();
    if (tid == 0) {
        float m = sm[0];
        for (int i = 1; i < 16; i++) m = fmaxf(m, sm[i]);
        sm[0] = m;
    }
    __syncthreads();
    mx = sm[0];
    __syncthreads();

    float sum = 0.0f;
#pragma unroll
    for (int i = 0; i < 4; i++) {
        v[i] = __expf(v[i] - mx);
        sum += v[i];
    }
#pragma unroll
    for (int o = 16; o; o >>= 1)
        sum += __shfl_xor_sync(0xffffffffu, sum, o);
    if (lane == 0) sm[warp] = sum;
    __syncthreads();
    if (tid == 0) {
        float s = 0.0f;
        for (int i = 1; i < 16; i++) s += sm[i];
        sm[0] += s;
    }
    __syncthreads();
    float inv = 1.0f / sm[0];
#pragma unroll
    for (int i = 0; i < 4; i++)
        wout[b * SS + tid + i * 512] = v[i] * inv;
}

// ---------------------------------------------------------------------------
// context[b,h] = sum_s w[b,s] * keys_fp16[b,s,h]  (written by score_kernel)
// ---------------------------------------------------------------------------
__global__ void context_kernel(const float* __restrict__ weights,
                               float* __restrict__ ctx) {
    int b = blockIdx.x;
    int chunk = blockIdx.y;
    int tid = threadIdx.x;
    const __half* kb = (const __half*)g_keys_h4 + (size_t)b * SS * HB;
    const float* wb = weights + b * SS;

    float4 acc = make_float4(0.f, 0.f, 0.f, 0.f);
    int s0 = chunk * (SS / 8);
#pragma unroll 4
    for (int s = s0; s < s0 + SS / 8; s++) {
        float w = wb[s];
        uint2 kv = *(const uint2*)(kb + (size_t)s * HB + tid * 4);
        float2 k0 = __half22float2(*(const __half2*)&kv.x);
        float2 k1 = __half22float2(*(const __half2*)&kv.y);
        acc.x += w * k0.x;
        acc.y += w * k0.y;
        acc.z += w * k1.x;
        acc.w += w * k1.y;
    }
    float* c = ctx + b * HB + tid * 4;
    atomicAdd(c + 0, acc.x);
    atomicAdd(c + 1, acc.y);
    atomicAdd(c + 2, acc.z);
    atomicAdd(c + 3, acc.w);
}

// ---------------------------------------------------------------------------
extern "C" void kernel_launch(void* const* d_in, const int* in_sizes, int n_in,
                              void* d_out, int out_size) {
    const float* query = (const float*)d_in[0];
    const float* keys  = (const float*)d_in[1];
    const float* Wa_w  = (const float*)d_in[2];
    const float* Wa_b  = (const float*)d_in[3];
    const float* Ua_w  = (const float*)d_in[4];
    const float* Ua_b  = (const float*)d_in[5];
    const float* Va_w  = (const float*)d_in[6];
    const float* Va_b  = (const float*)d_in[7];

    float* out = (float*)d_out;
    float* ctx = out;             // [NB*HB]
    float* wts = out + NB * HB;   // [NB*SS]

    cudaFuncSetAttribute(score_kernel, cudaFuncAttributeMaxDynamicSharedMemorySize,
                         SMEM_BYTES);

    // order chosen so score_kernel sits at launch index 3 (ncu samples it)
    cvt_ua_kernel<<<(HB * HB / 8) / 256, 256>>>(Ua_w);
    qproj_kernel<<<dim3(HB / 8, NB), 256>>>(query, Wa_w, Wa_b);
    init_kernel<<<(NB * HB + 255) / 256, 256>>>(ctx);
    score_kernel<<<dim3(HB / 256, MT / 128), 512, SMEM_BYTES>>>(keys, Ua_b, Va_w);
    softmax_kernel<<<NB, 512>>>(wts, Va_b);
    context_kernel<<<dim3(NB, 8), 256>>>(wts, ctx);
}

// round 16
// speedup vs baseline: 1.1091x; 1.1091x over previous
#include <cuda_runtime.h>
#include <cuda_fp16.h>
#include <cstdint>

static const int HB = 1024;   // hidden
static const int NB = 32;     // batch
static const int SS = 2048;   // seq
static const int MT = NB * SS;

__device__ float g_qproj[NB * HB];
__device__ float g_scores_part[16 * NB * SS];      // [bx*4+wn][m]
__device__ uint4 g_keys_h4[(size_t)NB * SS * HB / 8];  // keys as fp16, 128MB
__device__ uint4 g_ua_h4[HB * HB / 8];                 // Ua as fp16, 2MB

// ---------------------------------------------------------------------------
__device__ __forceinline__ uint32_t smem_u32(const void* p) {
    uint32_t a;
    asm("{ .reg .u64 t; cvta.to.shared.u64 t, %1; cvt.u32.u64 %0, t; }"
        : "=r"(a) : "l"(p));
    return a;
}

__device__ __forceinline__ void ldsm4(uint32_t* r, uint32_t addr) {
    asm volatile("ldmatrix.sync.aligned.m8n8.x4.shared.b16 {%0,%1,%2,%3}, [%4];"
                 : "=r"(r[0]), "=r"(r[1]), "=r"(r[2]), "=r"(r[3]) : "r"(addr));
}

__device__ __forceinline__ void mma16816(float* d, const uint32_t* a,
                                         uint32_t b0, uint32_t b1) {
    asm volatile(
        "mma.sync.aligned.m16n8k16.row.col.f32.f16.f16.f32 "
        "{%0,%1,%2,%3}, {%4,%5,%6,%7}, {%8,%9}, {%0,%1,%2,%3};"
        : "+f"(d[0]), "+f"(d[1]), "+f"(d[2]), "+f"(d[3])
        : "r"(a[0]), "r"(a[1]), "r"(a[2]), "r"(a[3]), "r"(b0), "r"(b1));
}

__device__ __forceinline__ void cpasync16(uint32_t saddr, const void* gaddr) {
    asm volatile("cp.async.cg.shared.global [%0], [%1], 16;"
                 :: "r"(saddr), "l"(gaddr));
}

__device__ __forceinline__ float fast_tanh(float x) {
    float y;
    asm("tanh.approx.f32 %0, %1;" : "=f"(y) : "f"(x));
    return y;
}

// fp32 -> fp16, 8 values -> one 16B word
__device__ __forceinline__ void cvt8_h(float4 a, float4 b, uint4& hi) {
    __half2 h0 = __float22half2_rn(make_float2(a.x, a.y));
    __half2 h1 = __float22half2_rn(make_float2(a.z, a.w));
    __half2 h2 = __float22half2_rn(make_float2(b.x, b.y));
    __half2 h3 = __float22half2_rn(make_float2(b.z, b.w));
    hi.x = *(uint32_t*)&h0; hi.y = *(uint32_t*)&h1;
    hi.z = *(uint32_t*)&h2; hi.w = *(uint32_t*)&h3;
}

// ---------------------------------------------------------------------------
// one kernel converts keys (units [0, KU)) and Ua (units [KU, KU+UU))
// ---------------------------------------------------------------------------
__global__ void cvt_all_kernel(const float* __restrict__ keys,
                               const float* __restrict__ ua) {
    const size_t KU = (size_t)NB * SS * HB / 8;
    size_t i = (size_t)blockIdx.x * blockDim.x + threadIdx.x;
    const float* src;
    uint4* dst;
    size_t u;
    if (i < KU) { src = keys; dst = g_keys_h4; u = i; }
    else        { src = ua;   dst = g_ua_h4;   u = i - KU; }
    const float4* p = (const float4*)src + u * 2;
    float4 a = p[0], b = p[1];
    uint4 h; cvt8_h(a, b, h);
    dst[u] = h;
}

// ---------------------------------------------------------------------------
__global__ void init_kernel(float* __restrict__ ctx) {
    int i = blockIdx.x * blockDim.x + threadIdx.x;
    if (i < NB * HB) ctx[i] = 0.0f;
}

// ---------------------------------------------------------------------------
// qproj: one block per k-row of Wa_w; row staged in smem, 8 warps x 4 batches.
// Wa traffic 4MB total (vs 128MB in the per-(k,b) mapping).
// ---------------------------------------------------------------------------
__global__ void qproj_kernel(const float* __restrict__ query,
                             const float* __restrict__ Wa_w,
                             const float* __restrict__ Wa_b) {
    __shared__ float wrow[HB];
    int k = blockIdx.x;
    int tid = threadIdx.x;
    int warp = tid >> 5, lane = tid & 31;

    // stage Wa_w[k,:] (1024 floats, 256 threads x 4)
    const float4* wsrc = (const float4*)(Wa_w + k * HB);
    ((float4*)wrow)[tid] = wsrc[tid];
    __syncthreads();

    float wb = Wa_b[k];
#pragma unroll
    for (int i = 0; i < 4; i++) {
        int b = warp * 4 + i;
        const float* q = query + b * HB;
        float acc = 0.0f;
#pragma unroll
        for (int j = 0; j < HB / 32; j++)
            acc += q[lane + 32 * j] * wrow[lane + 32 * j];
#pragma unroll
        for (int o = 16; o; o >>= 1)
            acc += __shfl_xor_sync(0xffffffffu, acc, o);
        if (lane == 0) g_qproj[b * HB + k] = acc + wb;
    }
}

// ---------------------------------------------------------------------------
// score GEMM (R9 exact): CTA tile 128(m) x 256(n), K-chunk 64, 512 thr
// (16 warps 4x4, warp tile 32x64). 4-stage cp.async ring on preconverted
// fp16. Epilogue fuses tanh + Va dot via smem-staged constants.
// ---------------------------------------------------------------------------
#define RSTRIDE 144
#define TB_OFF 18432
#define STG_SZ 55296
#define NSTG 4
#define OFF_QV 221184
#define OFF_VA 222208
#define SMEM_BYTES 223232
#define NCH 16

__global__ __launch_bounds__(512, 1)
void score_kernel(const float* __restrict__ Ua_b,
                  const float* __restrict__ Va_w) {
    extern __shared__ __align__(16) char smem[];
    const uint32_t sb = smem_u32(smem);
    const int tid = threadIdx.x;
    const int wid = tid >> 5, lane = tid & 31;
    const int lane16 = lane & 15, laneh = lane >> 4;
    const int n0 = blockIdx.x * 256;
    const int m0 = blockIdx.y * 128;
    const int b = m0 >> 11;                 // 128 | 2048

    const int wm = wid & 3, wn = wid >> 2;  // 4x4 warp grid, warp = 32m x 64n
    const int wrow0 = wm * 32, wcol0 = wn * 64;

    // epilogue constants
    if (tid < 256) {
        int n = n0 + tid;
        ((float*)(smem + OFF_QV))[tid] = g_qproj[b * HB + n] + Ua_b[n];
        ((float*)(smem + OFF_VA))[tid] = Va_w[n];
    }

    const __half* gA = (const __half*)g_keys_h4 + (size_t)m0 * HB;
    const __half* gB = (const __half*)g_ua_h4 + (size_t)n0 * HB;

    float acc[2][8][4];
#pragma unroll
    for (int mi = 0; mi < 2; mi++)
#pragma unroll
        for (int j = 0; j < 8; j++)
#pragma unroll
            for (int r = 0; r < 4; r++) acc[mi][j][r] = 0.0f;

    // issue one stage of cp.async (unit = 16B = 8 halves)
    auto issue = [&](int c) {
        const uint32_t sbase = sb + (c % NSTG) * STG_SZ;
        const int k0 = c * 64;
#pragma unroll
        for (int r = 0; r < 2; r++) {
            int unit = tid + 512 * r;
            int row = unit >> 3, u = unit & 7;
            cpasync16(sbase + row * RSTRIDE + u * 16,
                      gA + (size_t)row * HB + k0 + u * 8);
        }
#pragma unroll
        for (int r = 0; r < 4; r++) {
            int unit = tid + 512 * r;
            int row = unit >> 3, u = unit & 7;
            cpasync16(sbase + TB_OFF + row * RSTRIDE + u * 16,
                      gB + (size_t)row * HB + k0 + u * 8);
        }
        asm volatile("cp.async.commit_group;" ::: "memory");
    };

    issue(0);
    issue(1);
    issue(2);

    const uint32_t aAoff = (wrow0 + lane16) * RSTRIDE + laneh * 16;
    const uint32_t aBoff = TB_OFF + (wcol0 + lane16) * RSTRIDE + laneh * 16;

#pragma unroll 1
    for (int c = 0; c < NCH; c++) {
        if (c < NCH - 3)
            asm volatile("cp.async.wait_group 2;" ::: "memory");
        else if (c < NCH - 1)
            asm volatile("cp.async.wait_group 1;" ::: "memory");
        else
            asm volatile("cp.async.wait_group 0;" ::: "memory");
        __syncthreads();

        const uint32_t sbase = sb + (c % NSTG) * STG_SZ;
        const uint32_t aA = sbase + aAoff;
        const uint32_t aB = sbase + aBoff;

#pragma unroll
        for (int ks = 0; ks < 4; ks++) {
            const uint32_t kb = ks * 32;
            uint32_t ah[2][4];
            ldsm4(ah[0], aA + kb);
            ldsm4(ah[1], aA + kb + 16 * RSTRIDE);
#pragma unroll
            for (int nj = 0; nj < 4; nj++) {
                uint32_t bh[4];
                ldsm4(bh, aB + kb + nj * 16 * RSTRIDE);
#pragma unroll
                for (int h = 0; h < 2; h++) {
                    const int j = nj * 2 + h;
                    mma16816(acc[0][j], ah[0], bh[h], bh[h + 2]);
                    mma16816(acc[1][j], ah[1], bh[h], bh[h + 2]);
                }
            }
        }

        if (c + 3 < NCH) issue(c + 3);
    }

    // epilogue: part[row] = sum_n Va[n] * tanh(acc + qv[n])
    const float* sqv = (const float*)(smem + OFF_QV);
    const float* sva = (const float*)(smem + OFF_VA);
#pragma unroll
    for (int mi = 0; mi < 2; mi++) {
        float pr0 = 0.0f, pr1 = 0.0f;
#pragma unroll
        for (int j = 0; j < 8; j++) {
            int nl = wcol0 + j * 8 + (lane & 3) * 2;
            float q0 = sqv[nl], q1 = sqv[nl + 1];
            float v0 = sva[nl], v1 = sva[nl + 1];
            pr0 += v0 * fast_tanh(acc[mi][j][0] + q0) + v1 * fast_tanh(acc[mi][j][1] + q1);
            pr1 += v0 * fast_tanh(acc[mi][j][2] + q0) + v1 * fast_tanh(acc[mi][j][3] + q1);
        }
        pr0 += __shfl_xor_sync(0xffffffffu, pr0, 1);
        pr0 += __shfl_xor_sync(0xffffffffu, pr0, 2);
        pr1 += __shfl_xor_sync(0xffffffffu, pr1, 1);
        pr1 += __shfl_xor_sync(0xffffffffu, pr1, 2);
        if ((lane & 3) == 0) {
            int row = m0 + wrow0 + mi * 16 + (lane >> 2);
            int pidx = blockIdx.x * 4 + wn;
            g_scores_part[pidx * MT + row] = pr0;
            g_scores_part[pidx * MT + row + 8] = pr1;
        }
    }
}

// ---------------------------------------------------------------------------
// softmax: scores[m] = sum of 16 partials + Va_b, then softmax over S
// ---------------------------------------------------------------------------
__global__ void softmax_kernel(float* __restrict__ wout, const float* __restrict__ Va_b) {
    int b = blockIdx.x;
    int tid = threadIdx.x;
    int lane = tid & 31, warp = tid >> 5;
    float vb = Va_b[0];

    float v[4];
    float mx = -3.4e38f;
#pragma unroll
    for (int i = 0; i < 4; i++) {
        int m = b * SS + tid + i * 512;
        float s = vb;
#pragma unroll
        for (int p = 0; p < 16; p++) s += g_scores_part[p * MT + m];
        v[i] = s;
        mx = fmaxf(mx, v[i]);
    }
#pragma unroll
    for (int o = 16; o; o >>= 1)
        mx = fmaxf(mx, __shfl_xor_sync(0xffffffffu, mx, o));

    __shared__ float sm[16];
    if (lane == 0) sm[warp] = mx;
    __syncthreads();
    if (tid == 0) {
        float m = sm[0];
        for (int i = 1; i < 16; i++) m = fmaxf(m, sm[i]);
        sm[0] = m;
    }
    __syncthreads();
    mx = sm[0];
    __syncthreads();

    float sum = 0.0f;
#pragma unroll
    for (int i = 0; i < 4; i++) {
        v[i] = __expf(v[i] - mx);
        sum += v[i];
    }
#pragma unroll
    for (int o = 16; o; o >>= 1)
        sum += __shfl_xor_sync(0xffffffffu, sum, o);
    if (lane == 0) sm[warp] = sum;
    __syncthreads();
    if (tid == 0) {
        float s = 0.0f;
        for (int i = 1; i < 16; i++) s += sm[i];
        sm[0] += s;
    }
    __syncthreads();
    float inv = 1.0f / sm[0];
#pragma unroll
    for (int i = 0; i < 4; i++)
        wout[b * SS + tid + i * 512] = v[i] * inv;
}

// ---------------------------------------------------------------------------
// context[b,h] = sum_s w[b,s] * keys_fp16[b,s,h]
// ---------------------------------------------------------------------------
__global__ void context_kernel(const float* __restrict__ weights,
                               float* __restrict__ ctx) {
    int b = blockIdx.x;
    int chunk = blockIdx.y;
    int tid = threadIdx.x;
    const __half* kb = (const __half*)g_keys_h4 + (size_t)b * SS * HB;
    const float* wb = weights + b * SS;

    float4 acc = make_float4(0.f, 0.f, 0.f, 0.f);
    int s0 = chunk * (SS / 8);
#pragma unroll 4
    for (int s = s0; s < s0 + SS / 8; s++) {
        float w = wb[s];
        uint2 kv = *(const uint2*)(kb + (size_t)s * HB + tid * 4);
        float2 k0 = __half22float2(*(const __half2*)&kv.x);
        float2 k1 = __half22float2(*(const __half2*)&kv.y);
        acc.x += w * k0.x;
        acc.y += w * k0.y;
        acc.z += w * k1.x;
        acc.w += w * k1.y;
    }
    float* c = ctx + b * HB + tid * 4;
    atomicAdd(c + 0, acc.x);
    atomicAdd(c + 1, acc.y);
    atomicAdd(c + 2, acc.z);
    atomicAdd(c + 3, acc.w);
}

// ---------------------------------------------------------------------------
extern "C" void kernel_launch(void* const* d_in, const int* in_sizes, int n_in,
                              void* d_out, int out_size) {
    const float* query = (const float*)d_in[0];
    const float* keys  = (const float*)d_in[1];
    const float* Wa_w  = (const float*)d_in[2];
    const float* Wa_b  = (const float*)d_in[3];
    const float* Ua_w  = (const float*)d_in[4];
    const float* Ua_b  = (const float*)d_in[5];
    const float* Va_w  = (const float*)d_in[6];
    const float* Va_b  = (const float*)d_in[7];

    float* out = (float*)d_out;
    float* ctx = out;             // [NB*HB]
    float* wts = out + NB * HB;   // [NB*SS]

    cudaFuncSetAttribute(score_kernel, cudaFuncAttributeMaxDynamicSharedMemorySize,
                         SMEM_BYTES);

    const int total_units = (NB * SS * HB + HB * HB) / 8;   // keys + Ua

    // order chosen so score_kernel sits at launch index 3 (ncu samples it)
    cvt_all_kernel<<<total_units / 256, 256>>>(keys, Ua_w);
    qproj_kernel<<<HB, 256>>>(query, Wa_w, Wa_b);
    init_kernel<<<(NB * HB + 255) / 256, 256>>>(ctx);
    score_kernel<<<dim3(HB / 256, MT / 128), 512, SMEM_BYTES>>>(Ua_b, Va_w);
    softmax_kernel<<<NB, 512>>>(wts, Va_b);
    context_kernel<<<dim3(NB, 8), 256>>>(wts, ctx);
}